// round 15
// baseline (speedup 1.0000x reference)
#include <cuda_runtime.h>
#include <cuda_bf16.h>
#include <cuda_fp16.h>
#include <cstdint>
#include <cstddef>

#define N_NODES 20000
#define N_EDGES 320000
#define M_PAD   20224          // 158 * 128
#define F1 1152
#define F2 576
#define F3 288

// GEMM output (Y-cat) dims: N = K*Fout, padded to /128
#define NY1 6912               // 6*1152, 54*128 exact
#define NY2 2880               // 5*576
#define NY2P 2944              // 23*128
#define NY3 1440               // 5*288
#define NY3P 1536              // 12*128

// ---------------- scratch (device globals; allocation-free) ----------------
__device__ __half g_Y[(size_t)M_PAD * NY1];         // Y-cat in fp16 (read-once data)
__device__ float g_bufA[(size_t)M_PAD * F1];        // Clenshaw b buffers (fp32!)
__device__ float g_bufB[(size_t)M_PAD * F1];
__device__ float g_bufC[(size_t)M_PAD * F1];

// A ping-pong: fp16 (single-product GEMM)
__device__ __half g_A1f[(size_t)M_PAD * F1];
__device__ __half g_A2f[(size_t)M_PAD * F1];

// B = Wcat^T in fp16
__device__ __half g_W1h[(size_t)NY1 * F1];
__device__ __half g_W2h[(size_t)NY2P * F1];
__device__ __half g_W3h[(size_t)NY3P * F2];

__device__ int   g_deg[N_NODES];
__device__ int   g_fill[N_NODES];
__device__ int   g_rowptr[N_NODES + 1];
__device__ int   g_colS[N_EDGES];
__device__ float g_dis[N_NODES];

// ---------------- PTX helpers (base sm_103 target only) ----------------
__device__ __forceinline__ uint32_t smem_u32(const void* p) {
    uint32_t a;
    asm("{ .reg .u64 t; cvta.to.shared.u64 t, %1; cvt.u32.u64 %0, t; }" : "=r"(a) : "l"(p));
    return a;
}

#define CP_ASYNC16(dst, src) \
    asm volatile("cp.async.cg.shared.global [%0], [%1], 16;" :: "r"(dst), "l"(src) : "memory")
#define CP_COMMIT() asm volatile("cp.async.commit_group;" ::: "memory")
#define CP_WAIT1()  asm volatile("cp.async.wait_group 1;" ::: "memory")

#define LDMATRIX_X4(r0, r1, r2, r3, addr) \
    asm volatile("ldmatrix.sync.aligned.m8n8.x4.shared.b16 {%0,%1,%2,%3}, [%4];" \
                 : "=r"(r0), "=r"(r1), "=r"(r2), "=r"(r3) : "r"(addr))

#define MMA_F16(d, a, b) \
    asm volatile("mma.sync.aligned.m16n8k16.row.col.f32.f16.f16.f32 " \
                 "{%0,%1,%2,%3}, {%4,%5,%6,%7}, {%8,%9}, {%0,%1,%2,%3};" \
                 : "+f"((d)[0]), "+f"((d)[1]), "+f"((d)[2]), "+f"((d)[3]) \
                 : "r"((a)[0]), "r"((a)[1]), "r"((a)[2]), "r"((a)[3]), \
                   "r"((b)[0]), "r"((b)[1]))

// fp32 vector loads/stores with streaming hint
__device__ __forceinline__ float4 ldcs4(const float4* p) {
    float4 v;
    asm volatile("ld.global.cs.v4.f32 {%0,%1,%2,%3}, [%4];"
                 : "=f"(v.x), "=f"(v.y), "=f"(v.z), "=f"(v.w) : "l"(p));
    return v;
}
__device__ __forceinline__ void stcs4(float4* p, float4 v) {
    asm volatile("st.global.cs.v4.f32 [%0], {%1,%2,%3,%4};"
                 :: "l"(p), "f"(v.x), "f"(v.y), "f"(v.z), "f"(v.w) : "memory");
}
// half loads: 4 halves -> float4 (default and streaming)
__device__ __forceinline__ float4 ld4h(const __half* p) {
    uint2 u = *reinterpret_cast<const uint2*>(p);
    __half2 h0 = *reinterpret_cast<__half2*>(&u.x);
    __half2 h1 = *reinterpret_cast<__half2*>(&u.y);
    float2 f0 = __half22float2(h0), f1 = __half22float2(h1);
    return make_float4(f0.x, f0.y, f1.x, f1.y);
}
__device__ __forceinline__ float4 ldcs4h(const __half* p) {
    uint2 u;
    asm volatile("ld.global.cs.v2.b32 {%0,%1}, [%2];" : "=r"(u.x), "=r"(u.y) : "l"(p));
    __half2 h0 = *reinterpret_cast<__half2*>(&u.x);
    __half2 h1 = *reinterpret_cast<__half2*>(&u.y);
    float2 f0 = __half22float2(h0), f1 = __half22float2(h1);
    return make_float4(f0.x, f0.y, f1.x, f1.y);
}
__device__ __forceinline__ void stcs_h2(__half* p, float a, float b) {
    __half2 h = __halves2half2(__float2half_rn(a), __float2half_rn(b));
    uint32_t u = *reinterpret_cast<uint32_t*>(&h);
    asm volatile("st.global.cs.b32 [%0], %1;" :: "l"(p), "r"(u) : "memory");
}

// ---------------- graph setup ----------------
__global__ void zero_counts_kernel() {
    int i = blockIdx.x * blockDim.x + threadIdx.x;
    if (i < N_NODES) { g_deg[i] = 0; g_fill[i] = 0; }
}
__global__ void hist_kernel(const int* __restrict__ row, const int* __restrict__ col) {
    int e = blockIdx.x * blockDim.x + threadIdx.x;
    if (e < N_EDGES) {
        int r = row[e];
        if (r != col[e]) atomicAdd(&g_deg[r], 1);
    }
}
// scan + dis fused
__global__ void scan_kernel() {
    __shared__ int sums[1024];
    int t = threadIdx.x;
    const int CHUNK = (N_NODES + 1023) / 1024;
    int lo = t * CHUNK, hi = lo + CHUNK;
    if (hi > N_NODES) hi = N_NODES;
    int s = 0;
    for (int i = lo; i < hi; i++) s += g_deg[i];
    sums[t] = s;
    __syncthreads();
    for (int off = 1; off < 1024; off <<= 1) {
        int v = (t >= off) ? sums[t - off] : 0;
        __syncthreads();
        sums[t] += v;
        __syncthreads();
    }
    int run = (t == 0) ? 0 : sums[t - 1];
    for (int i = lo; i < hi; i++) {
        g_rowptr[i] = run;
        int d = g_deg[i];
        run += d;
        g_dis[i] = (d > 0) ? rsqrtf((float)d) : 0.0f;
    }
    if (t == 1023) g_rowptr[N_NODES] = sums[1023];
}
__global__ void scatter_kernel(const int* __restrict__ row, const int* __restrict__ col) {
    int e = blockIdx.x * blockDim.x + threadIdx.x;
    if (e < N_EDGES) {
        int r = row[e], c = col[e];
        if (r != c) {
            int pos = g_rowptr[r] + atomicAdd(&g_fill[r], 1);
            g_colS[pos] = c;
        }
    }
}

// ---------------- conversion helpers ----------------
__global__ void convert_split_kernel(const float* __restrict__ src, int F,
                                     __half* __restrict__ af) {
    int total = M_PAD * F;
    for (int idx = blockIdx.x * blockDim.x + threadIdx.x; idx < total;
         idx += gridDim.x * blockDim.x) {
        int r = idx / F, c = idx - r * F;
        float v = (r < N_NODES) ? src[(size_t)r * F + c] : 0.0f;
        af[(size_t)r * F + c] = __float2half_rn(v);
    }
}

__global__ void wsplit2_kernel(const float* __restrict__ W, int Fin, int Fout,
                               __half* __restrict__ hi) {
    __shared__ float tile[32][33];
    int kk0 = blockIdx.x * 32, n0 = blockIdx.y * 32, k = blockIdx.z;
    int tx = threadIdx.x, ty = threadIdx.y;
    const float* Wk = W + (size_t)k * Fin * Fout;
#pragma unroll
    for (int r = 0; r < 32; r += 8)
        tile[ty + r][tx] = Wk[(size_t)(kk0 + ty + r) * Fout + n0 + tx];
    __syncthreads();
#pragma unroll
    for (int r = 0; r < 32; r += 8) {
        float v = tile[tx][ty + r];
        size_t o = (size_t)(k * Fout + n0 + ty + r) * Fin + kk0 + tx;
        hi[o] = __float2half_rn(v);
    }
}

// ---------------- Clenshaw propagation ----------------
// out = alpha*(L~ g) + addY - sub   (sub nullable)
// g: fp16 when GH (first prop of layer: Y slice), else fp32 b buffer.
// addY: ALWAYS a fp16 Y slice, streamed.
// sub: fp16 Y slice when SH, else fp32 b buffer; streamed either way.
// Strides ldG/ldA/ldS in ELEMENTS. b buffers stay fp32.
template <int F, int THREADS, bool FINAL, bool GH, bool SH>
__global__ void prop2_kernel(const void* __restrict__ g, int ldG,
                             const __half* __restrict__ addY, int ldA,
                             const void* __restrict__ sub, int ldS,
                             float alpha,
                             float* __restrict__ outF, int ldO4,
                             const float* __restrict__ bias,
                             __half* __restrict__ af, int ldCat) {
    constexpr int F4 = F / 4;
    constexpr int NF = F4 / THREADS;
    static_assert(NF * THREADS == F4, "exact fit required");
    constexpr int ECHUNK = 128;
    __shared__ int   s_col[ECHUNK];
    __shared__ float s_w[ECHUNK];

    int i = blockIdx.x;
    int tid = threadIdx.x;
    bool real = (i < N_NODES);
    int s0 = real ? g_rowptr[i] : 0;
    int s1 = real ? g_rowptr[i + 1] : 0;

    // prefetch addY / sub rows (streamed; overlaps the gather loop)
    float4 addv[NF], subv[NF];
    {
        const __half* arow = addY + (size_t)i * ldA;
#pragma unroll
        for (int j = 0; j < NF; j++) {
            int f4 = (tid + j * THREADS) * 4;
            addv[j] = ldcs4h(arow + f4);
            if (sub) {
                if (SH) subv[j] = ldcs4h((const __half*)sub + (size_t)i * ldS + f4);
                else    subv[j] = ldcs4(reinterpret_cast<const float4*>(
                                        (const float*)sub + (size_t)i * ldS) + (tid + j * THREADS));
            } else subv[j] = make_float4(0.f, 0.f, 0.f, 0.f);
        }
    }

    float ax[NF], ay[NF], az[NF], aw[NF];
#pragma unroll
    for (int j = 0; j < NF; j++) { ax[j] = 0.f; ay[j] = 0.f; az[j] = 0.f; aw[j] = 0.f; }

    int e = s0;
    while (e < s1) {
        int cnt = s1 - e; if (cnt > ECHUNK) cnt = ECHUNK;
        __syncthreads();
        for (int q = tid; q < cnt; q += THREADS) {
            int c = g_colS[e + q];
            s_col[q] = c;
            s_w[q] = g_dis[c];
        }
        __syncthreads();

        int q = 0;
        for (; q + 4 <= cnt; q += 4) {
            int c0 = s_col[q],     c1 = s_col[q + 1];
            int c2 = s_col[q + 2], c3 = s_col[q + 3];
            float w0 = s_w[q],     w1 = s_w[q + 1];
            float w2 = s_w[q + 2], w3 = s_w[q + 3];
#pragma unroll
            for (int j = 0; j < NF; j++) {
                int f = tid + j * THREADS;
                float4 v0, v1, v2, v3;
                if (GH) {
                    const __half* gb = (const __half*)g;
                    v0 = ld4h(gb + (size_t)c0 * ldG + f * 4);
                    v1 = ld4h(gb + (size_t)c1 * ldG + f * 4);
                    v2 = ld4h(gb + (size_t)c2 * ldG + f * 4);
                    v3 = ld4h(gb + (size_t)c3 * ldG + f * 4);
                } else {
                    const float* gb = (const float*)g;
                    v0 = reinterpret_cast<const float4*>(gb + (size_t)c0 * ldG)[f];
                    v1 = reinterpret_cast<const float4*>(gb + (size_t)c1 * ldG)[f];
                    v2 = reinterpret_cast<const float4*>(gb + (size_t)c2 * ldG)[f];
                    v3 = reinterpret_cast<const float4*>(gb + (size_t)c3 * ldG)[f];
                }
                ax[j] += w0 * v0.x + w1 * v1.x + w2 * v2.x + w3 * v3.x;
                ay[j] += w0 * v0.y + w1 * v1.y + w2 * v2.y + w3 * v3.y;
                az[j] += w0 * v0.z + w1 * v1.z + w2 * v2.z + w3 * v3.z;
                aw[j] += w0 * v0.w + w1 * v1.w + w2 * v2.w + w3 * v3.w;
            }
        }
        for (; q < cnt; q++) {
            int c = s_col[q];
            float s = s_w[q];
#pragma unroll
            for (int j = 0; j < NF; j++) {
                int f = tid + j * THREADS;
                float4 v;
                if (GH) v = ld4h((const __half*)g + (size_t)c * ldG + f * 4);
                else    v = reinterpret_cast<const float4*>((const float*)g + (size_t)c * ldG)[f];
                ax[j] += s * v.x; ay[j] += s * v.y;
                az[j] += s * v.z; aw[j] += s * v.w;
            }
        }
        e += cnt;
    }

    float sc = real ? (-alpha * g_dis[i]) : 0.0f;

#pragma unroll
    for (int j = 0; j < NF; j++) {
        int f = tid + j * THREADS;
        float4 r;
        r.x = sc * ax[j] + addv[j].x - subv[j].x;
        r.y = sc * ay[j] + addv[j].y - subv[j].y;
        r.z = sc * az[j] + addv[j].z - subv[j].z;
        r.w = sc * aw[j] + addv[j].w - subv[j].w;
        if (FINAL) {
            if (real) {
                const float4 bv = reinterpret_cast<const float4*>(bias)[f];
                r.x = fmaxf(r.x + bv.x, 0.f); r.y = fmaxf(r.y + bv.y, 0.f);
                r.z = fmaxf(r.z + bv.z, 0.f); r.w = fmaxf(r.w + bv.w, 0.f);
            } else {
                r.x = r.y = r.z = r.w = 0.f;
            }
            if (af) {
                size_t o = (size_t)i * ldCat + (size_t)f * 4;
                __half2* fp = reinterpret_cast<__half2*>(af + o);
                fp[0] = __halves2half2(__float2half_rn(r.x), __float2half_rn(r.y));
                fp[1] = __halves2half2(__float2half_rn(r.z), __float2half_rn(r.w));
            }
            if (outF && real)
                stcs4(reinterpret_cast<float4*>(outF) + (size_t)i * ldO4 + f, r);
        } else {
            // next prop gathers this buffer: default policy (keep in L2)
            reinterpret_cast<float4*>(outF)[(size_t)i * ldO4 + f] = r;
        }
    }
}

// ---------------- single-product fp16 mma.sync GEMM ----------------
// Y[M x N] (fp16 out, ld=ldC halves) = Af16 x Bh16^T, fp32 accumulate.
// 128x128 CTA, 4 warps of 64x64, 3 stages XOR-swizzled, 1 sync/k-tile, 3 CTA/SM.
#define GBK     32
#define TILE_B  (128 * 64)
#define STG_B   (2 * TILE_B)              // A, B tiles only
#define SMEM_TOTAL_GEMM (3 * STG_B)       // 49152

__device__ __forceinline__ uint32_t sw_off(int r, int c16) {
    return (uint32_t)(r * 64 + ((c16 ^ ((r >> 1) & 3)) * 16));
}

__global__ void __launch_bounds__(128, 3)
gemm_fused_kernel(const __half* __restrict__ Af, const __half* __restrict__ Bh,
                  __half* __restrict__ C, int N, int ldC, int K) {
    extern __shared__ char smem[];
    uint32_t sb = smem_u32(smem);
    int tid = threadIdx.x;
    int lane = tid & 31;
    int wid = tid >> 5;
    int bm = blockIdx.y * 128;
    int bn = blockIdx.x * 128;

    const int kt = K / GBK;

    int wm = (wid & 1) * 64;
    int wn = (wid >> 1) * 64;

    float d[4][8][4];
#pragma unroll
    for (int i = 0; i < 4; i++)
#pragma unroll
        for (int j = 0; j < 8; j++)
#pragma unroll
            for (int q = 0; q < 4; q++) d[i][j][q] = 0.f;

    size_t ld = (size_t)K * 2;   // bytes per row
    auto issue = [&](int it) {
        int kk = it * GBK;
        int s = it % 3;
        uint32_t base = sb + s * STG_B;
        const char* srcA = (const char*)(Af + (size_t)bm * K + kk);
        const char* srcB = (const char*)(Bh + (size_t)bn * K + kk);
#pragma unroll
        for (int i = 0; i < 4; i++) {
            int v = tid + i * 128;
            int r = v >> 2, p = v & 3;
            CP_ASYNC16(base + sw_off(r, p), srcA + (size_t)r * ld + p * 16);
        }
#pragma unroll
        for (int i = 0; i < 4; i++) {
            int v = tid + i * 128;
            int r = v >> 2, p = v & 3;
            CP_ASYNC16(base + TILE_B + sw_off(r, p), srcB + (size_t)r * ld + p * 16);
        }
    };

    issue(0); CP_COMMIT();
    if (kt > 1) issue(1);
    CP_COMMIT();

    int lrow = lane & 15;
    int lcol = (lane >> 4) * 8;

    uint32_t arow[4], brow[4];
#pragma unroll
    for (int i = 0; i < 4; i++) {
        int rr = wm + i * 16 + lrow;
        arow[i] = (uint32_t)(rr * 64) | ((uint32_t)((rr >> 1) & 3) << 28);
    }
#pragma unroll
    for (int jp = 0; jp < 4; jp++) {
        int rr = wn + jp * 16 + lrow;
        brow[jp] = (uint32_t)(rr * 64) | ((uint32_t)((rr >> 1) & 3) << 28);
    }

    for (int it = 0; it < kt; ++it) {
        CP_WAIT1();
        __syncthreads();

        if (it + 2 < kt) issue(it + 2);
        CP_COMMIT();

        int s = it % 3;
        uint32_t sA = sb + s * STG_B;
        uint32_t sB = sA + TILE_B;

#pragma unroll
        for (int ks = 0; ks < GBK; ks += 16) {
            uint32_t cch = (uint32_t)((ks + lcol) >> 3);

            uint32_t a[4][4], b[8][2];
#pragma unroll
            for (int i = 0; i < 4; i++) {
                uint32_t off = (arow[i] & 0x0fffffffu) + ((cch ^ (arow[i] >> 28)) << 4);
                LDMATRIX_X4(a[i][0], a[i][1], a[i][2], a[i][3], sA + off);
            }
#pragma unroll
            for (int jp = 0; jp < 4; jp++) {
                uint32_t off = (brow[jp] & 0x0fffffffu) + ((cch ^ (brow[jp] >> 28)) << 4);
                uint32_t q0, q1, q2, q3;
                LDMATRIX_X4(q0, q1, q2, q3, sB + off);
                b[2 * jp][0] = q0; b[2 * jp][1] = q2;
                b[2 * jp + 1][0] = q1; b[2 * jp + 1][1] = q3;
            }
#pragma unroll
            for (int i = 0; i < 4; i++)
#pragma unroll
                for (int j = 0; j < 8; j++)
                    MMA_F16(d[i][j], a[i], b[j]);
        }
    }

    // epilogue: streamed fp16 Y writes (pad rows of A are zero -> Y pad rows zero)
    int gr = lane >> 2;
    int gc = (lane & 3) * 2;
#pragma unroll
    for (int i = 0; i < 4; i++) {
#pragma unroll
        for (int j = 0; j < 8; j++) {
            int colb = bn + wn + j * 8 + gc;
            if (colb >= N) continue;
            int row0 = bm + wm + i * 16 + gr;
            int row1 = row0 + 8;
            stcs_h2(&C[(size_t)row0 * ldC + colb], d[i][j][0], d[i][j][1]);
            stcs_h2(&C[(size_t)row1 * ldC + colb], d[i][j][2], d[i][j][3]);
        }
    }
}

// ---------------- host orchestration ----------------
extern "C" void kernel_launch(void* const* d_in, const int* in_sizes, int n_in,
                              void* d_out, int out_size) {
    const float* x   = (const float*)d_in[0];
    const int*   row = (const int*)d_in[1];
    const int*   col = (const int*)d_in[2];
    const float* W1  = (const float*)d_in[3];
    const float* b1  = (const float*)d_in[4];
    const float* W2  = (const float*)d_in[5];
    const float* b2  = (const float*)d_in[6];
    const float* W3  = (const float*)d_in[7];
    const float* b3  = (const float*)d_in[8];
    float* out = (float*)d_out;

    float *bufA, *bufB, *bufC;
    __half *Y, *A1f, *A2f, *W1h, *W2h, *W3h;
    cudaGetSymbolAddress((void**)&Y, g_Y);
    cudaGetSymbolAddress((void**)&bufA, g_bufA);
    cudaGetSymbolAddress((void**)&bufB, g_bufB);
    cudaGetSymbolAddress((void**)&bufC, g_bufC);
    cudaGetSymbolAddress((void**)&A1f, g_A1f);
    cudaGetSymbolAddress((void**)&A2f, g_A2f);
    cudaGetSymbolAddress((void**)&W1h, g_W1h);
    cudaGetSymbolAddress((void**)&W2h, g_W2h);
    cudaGetSymbolAddress((void**)&W3h, g_W3h);

    cudaFuncSetAttribute(gemm_fused_kernel,
                         cudaFuncAttributeMaxDynamicSharedMemorySize, SMEM_TOTAL_GEMM);

    // ---- graph setup ----
    zero_counts_kernel<<<(N_NODES + 255) / 256, 256>>>();
    hist_kernel<<<(N_EDGES + 255) / 256, 256>>>(row, col);
    scan_kernel<<<1, 1024>>>();
    scatter_kernel<<<(N_EDGES + 255) / 256, 256>>>(row, col);

    // ---- conversions ----
    convert_split_kernel<<<4096, 256>>>(x, F1, A1f);
    wsplit2_kernel<<<dim3(F1 / 32, F1 / 32, 6), dim3(32, 8)>>>(W1, F1, F1, W1h);
    wsplit2_kernel<<<dim3(F1 / 32, F2 / 32, 5), dim3(32, 8)>>>(W2, F1, F2, W2h);
    wsplit2_kernel<<<dim3(F2 / 32, F3 / 32, 5), dim3(32, 8)>>>(W3, F2, F3, W3h);

    // ================= Layer 1: K=6, Fout=1152 =================
    gemm_fused_kernel<<<dim3(NY1 / 128, M_PAD / 128), 128, SMEM_TOTAL_GEMM>>>(
        A1f, W1h, Y, NY1, NY1, F1);
    {
        const int ldY = NY1;            // element stride (halves)
        const int ldF = F1;             // element stride (floats)
        const int ldF4 = F1 / 4;
        // Clenshaw: b5 = Y5; b4..b1; S = Y0 + L~b1 - b2
        prop2_kernel<F1, 96, false, true,  false><<<M_PAD, 96>>>(
            Y + 5 * F1, ldY, Y + 4 * F1, ldY, nullptr, 0, 2.0f, bufA, ldF4, nullptr, nullptr, 0);
        prop2_kernel<F1, 96, false, false, true ><<<M_PAD, 96>>>(
            bufA, ldF, Y + 3 * F1, ldY, Y + 5 * F1, ldY, 2.0f, bufB, ldF4, nullptr, nullptr, 0);
        prop2_kernel<F1, 96, false, false, false><<<M_PAD, 96>>>(
            bufB, ldF, Y + 2 * F1, ldY, bufA, ldF, 2.0f, bufC, ldF4, nullptr, nullptr, 0);
        prop2_kernel<F1, 96, false, false, false><<<M_PAD, 96>>>(
            bufC, ldF, Y + 1 * F1, ldY, bufB, ldF, 2.0f, bufA, ldF4, nullptr, nullptr, 0);
        prop2_kernel<F1, 96, true,  false, false><<<M_PAD, 96>>>(
            bufA, ldF, Y + 0, ldY, bufC, ldF, 1.0f, nullptr, 0, b1, A2f, F1);
    }

    // ================= Layer 2: K=5, Fout=576 =================
    gemm_fused_kernel<<<dim3(NY2P / 128, M_PAD / 128), 128, SMEM_TOTAL_GEMM>>>(
        A2f, W2h, Y, NY2, NY2P, F1);
    {
        const int ldY = NY2P;
        const int ldF = F2;
        const int ldF4 = F2 / 4;
        prop2_kernel<F2, 144, false, true,  false><<<M_PAD, 144>>>(
            Y + 4 * F2, ldY, Y + 3 * F2, ldY, nullptr, 0, 2.0f, bufA, ldF4, nullptr, nullptr, 0);
        prop2_kernel<F2, 144, false, false, true ><<<M_PAD, 144>>>(
            bufA, ldF, Y + 2 * F2, ldY, Y + 4 * F2, ldY, 2.0f, bufB, ldF4, nullptr, nullptr, 0);
        prop2_kernel<F2, 144, false, false, false><<<M_PAD, 144>>>(
            bufB, ldF, Y + 1 * F2, ldY, bufA, ldF, 2.0f, bufC, ldF4, nullptr, nullptr, 0);
        prop2_kernel<F2, 144, true,  false, false><<<M_PAD, 144>>>(
            bufC, ldF, Y + 0, ldY, bufB, ldF, 1.0f, nullptr, 0, b2, A1f, F2);
    }

    // ================= Layer 3: K=5, Fout=288 =================
    gemm_fused_kernel<<<dim3(NY3P / 128, M_PAD / 128), 128, SMEM_TOTAL_GEMM>>>(
        A1f, W3h, Y, NY3, NY3P, F2);
    {
        const int ldY = NY3P;
        const int ldF = F3;
        const int ldF4 = F3 / 4;
        prop2_kernel<F3, 72, false, true,  false><<<M_PAD, 72>>>(
            Y + 4 * F3, ldY, Y + 3 * F3, ldY, nullptr, 0, 2.0f, bufA, ldF4, nullptr, nullptr, 0);
        prop2_kernel<F3, 72, false, false, true ><<<M_PAD, 72>>>(
            bufA, ldF, Y + 2 * F3, ldY, Y + 4 * F3, ldY, 2.0f, bufB, ldF4, nullptr, nullptr, 0);
        prop2_kernel<F3, 72, false, false, false><<<M_PAD, 72>>>(
            bufB, ldF, Y + 1 * F3, ldY, bufA, ldF, 2.0f, bufC, ldF4, nullptr, nullptr, 0);
        prop2_kernel<F3, 72, true,  false, false><<<M_PAD, 72>>>(
            bufC, ldF, Y + 0, ldY, bufB, ldF, 1.0f, out, ldF4, b3, nullptr, 0);
    }
}

// round 16
// speedup vs baseline: 1.0068x; 1.0068x over previous
#include <cuda_runtime.h>
#include <cuda_bf16.h>
#include <cuda_fp16.h>
#include <cstdint>
#include <cstddef>

#define N_NODES 20000
#define N_EDGES 320000
#define M_PAD   20224          // 158 * 128
#define F1 1152
#define F2 576
#define F3 288

// GEMM output (Y-cat) dims: N = K*Fout, padded to /128
#define NY1 6912               // 6*1152, 54*128 exact
#define NY2 2880               // 5*576
#define NY2P 2944              // 23*128
#define NY3 1440               // 5*288
#define NY3P 1536              // 12*128

// ---------------- scratch (device globals; allocation-free) ----------------
__device__ __half g_Y[(size_t)M_PAD * NY1];         // Y-cat in fp16 (read-once data)
__device__ float g_bufA[(size_t)M_PAD * F1];        // Clenshaw b buffers (fp32!)
__device__ float g_bufB[(size_t)M_PAD * F1];
__device__ float g_bufC[(size_t)M_PAD * F1];

// A ping-pong: fp16 (single-product GEMM)
__device__ __half g_A1f[(size_t)M_PAD * F1];
__device__ __half g_A2f[(size_t)M_PAD * F1];

// B = Wcat^T in fp16
__device__ __half g_W1h[(size_t)NY1 * F1];
__device__ __half g_W2h[(size_t)NY2P * F1];
__device__ __half g_W3h[(size_t)NY3P * F2];

__device__ int   g_deg[N_NODES];
__device__ int   g_fill[N_NODES];
__device__ int   g_rowptr[N_NODES + 1];
__device__ int   g_colS[N_EDGES];
__device__ float g_dis[N_NODES];

// ---------------- PTX helpers (base sm_103 target only) ----------------
__device__ __forceinline__ uint32_t smem_u32(const void* p) {
    uint32_t a;
    asm("{ .reg .u64 t; cvta.to.shared.u64 t, %1; cvt.u32.u64 %0, t; }" : "=r"(a) : "l"(p));
    return a;
}

#define CP_ASYNC16(dst, src) \
    asm volatile("cp.async.cg.shared.global [%0], [%1], 16;" :: "r"(dst), "l"(src) : "memory")
#define CP_COMMIT() asm volatile("cp.async.commit_group;" ::: "memory")
#define CP_WAIT1()  asm volatile("cp.async.wait_group 1;" ::: "memory")

#define LDMATRIX_X4(r0, r1, r2, r3, addr) \
    asm volatile("ldmatrix.sync.aligned.m8n8.x4.shared.b16 {%0,%1,%2,%3}, [%4];" \
                 : "=r"(r0), "=r"(r1), "=r"(r2), "=r"(r3) : "r"(addr))

#define MMA_F16(d, a, b) \
    asm volatile("mma.sync.aligned.m16n8k16.row.col.f32.f16.f16.f32 " \
                 "{%0,%1,%2,%3}, {%4,%5,%6,%7}, {%8,%9}, {%0,%1,%2,%3};" \
                 : "+f"((d)[0]), "+f"((d)[1]), "+f"((d)[2]), "+f"((d)[3]) \
                 : "r"((a)[0]), "r"((a)[1]), "r"((a)[2]), "r"((a)[3]), \
                   "r"((b)[0]), "r"((b)[1]))

// fp32 vector loads/stores with streaming hint
__device__ __forceinline__ float4 ldcs4(const float4* p) {
    float4 v;
    asm volatile("ld.global.cs.v4.f32 {%0,%1,%2,%3}, [%4];"
                 : "=f"(v.x), "=f"(v.y), "=f"(v.z), "=f"(v.w) : "l"(p));
    return v;
}
__device__ __forceinline__ void stcs4(float4* p, float4 v) {
    asm volatile("st.global.cs.v4.f32 [%0], {%1,%2,%3,%4};"
                 :: "l"(p), "f"(v.x), "f"(v.y), "f"(v.z), "f"(v.w) : "memory");
}
// half loads: 4 halves -> float4 (default and streaming)
__device__ __forceinline__ float4 ld4h(const __half* p) {
    uint2 u = *reinterpret_cast<const uint2*>(p);
    __half2 h0 = *reinterpret_cast<__half2*>(&u.x);
    __half2 h1 = *reinterpret_cast<__half2*>(&u.y);
    float2 f0 = __half22float2(h0), f1 = __half22float2(h1);
    return make_float4(f0.x, f0.y, f1.x, f1.y);
}
__device__ __forceinline__ float4 ldcs4h(const __half* p) {
    uint2 u;
    asm volatile("ld.global.cs.v2.b32 {%0,%1}, [%2];" : "=r"(u.x), "=r"(u.y) : "l"(p));
    __half2 h0 = *reinterpret_cast<__half2*>(&u.x);
    __half2 h1 = *reinterpret_cast<__half2*>(&u.y);
    float2 f0 = __half22float2(h0), f1 = __half22float2(h1);
    return make_float4(f0.x, f0.y, f1.x, f1.y);
}
__device__ __forceinline__ void stcs_h2(__half* p, float a, float b) {
    __half2 h = __halves2half2(__float2half_rn(a), __float2half_rn(b));
    uint32_t u = *reinterpret_cast<uint32_t*>(&h);
    asm volatile("st.global.cs.b32 [%0], %1;" :: "l"(p), "r"(u) : "memory");
}

// ---------------- graph setup ----------------
__global__ void zero_counts_kernel() {
    int i = blockIdx.x * blockDim.x + threadIdx.x;
    if (i < N_NODES) { g_deg[i] = 0; g_fill[i] = 0; }
}
__global__ void hist_kernel(const int* __restrict__ row, const int* __restrict__ col) {
    int e = blockIdx.x * blockDim.x + threadIdx.x;
    if (e < N_EDGES) {
        int r = row[e];
        if (r != col[e]) atomicAdd(&g_deg[r], 1);
    }
}
// scan + dis fused
__global__ void scan_kernel() {
    __shared__ int sums[1024];
    int t = threadIdx.x;
    const int CHUNK = (N_NODES + 1023) / 1024;
    int lo = t * CHUNK, hi = lo + CHUNK;
    if (hi > N_NODES) hi = N_NODES;
    int s = 0;
    for (int i = lo; i < hi; i++) s += g_deg[i];
    sums[t] = s;
    __syncthreads();
    for (int off = 1; off < 1024; off <<= 1) {
        int v = (t >= off) ? sums[t - off] : 0;
        __syncthreads();
        sums[t] += v;
        __syncthreads();
    }
    int run = (t == 0) ? 0 : sums[t - 1];
    for (int i = lo; i < hi; i++) {
        g_rowptr[i] = run;
        int d = g_deg[i];
        run += d;
        g_dis[i] = (d > 0) ? rsqrtf((float)d) : 0.0f;
    }
    if (t == 1023) g_rowptr[N_NODES] = sums[1023];
}
__global__ void scatter_kernel(const int* __restrict__ row, const int* __restrict__ col) {
    int e = blockIdx.x * blockDim.x + threadIdx.x;
    if (e < N_EDGES) {
        int r = row[e], c = col[e];
        if (r != c) {
            int pos = g_rowptr[r] + atomicAdd(&g_fill[r], 1);
            g_colS[pos] = c;
        }
    }
}

// ---------------- conversion helpers ----------------
__global__ void convert_split_kernel(const float* __restrict__ src, int F,
                                     __half* __restrict__ af) {
    int total = M_PAD * F;
    for (int idx = blockIdx.x * blockDim.x + threadIdx.x; idx < total;
         idx += gridDim.x * blockDim.x) {
        int r = idx / F, c = idx - r * F;
        float v = (r < N_NODES) ? src[(size_t)r * F + c] : 0.0f;
        af[(size_t)r * F + c] = __float2half_rn(v);
    }
}

__global__ void wsplit2_kernel(const float* __restrict__ W, int Fin, int Fout,
                               __half* __restrict__ hi) {
    __shared__ float tile[32][33];
    int kk0 = blockIdx.x * 32, n0 = blockIdx.y * 32, k = blockIdx.z;
    int tx = threadIdx.x, ty = threadIdx.y;
    const float* Wk = W + (size_t)k * Fin * Fout;
#pragma unroll
    for (int r = 0; r < 32; r += 8)
        tile[ty + r][tx] = Wk[(size_t)(kk0 + ty + r) * Fout + n0 + tx];
    __syncthreads();
#pragma unroll
    for (int r = 0; r < 32; r += 8) {
        float v = tile[tx][ty + r];
        size_t o = (size_t)(k * Fout + n0 + ty + r) * Fin + kk0 + tx;
        hi[o] = __float2half_rn(v);
    }
}

// ---------------- Clenshaw propagation ----------------
// out = alpha*(L~ g) + addY - sub   (sub nullable)
// g: fp16 when GH (first prop of layer: Y slice), else fp32 b buffer.
// addY: ALWAYS a fp16 Y slice, streamed.
// sub: fp16 Y slice when SH, else fp32 b buffer; streamed either way.
// Strides ldG/ldA/ldS in ELEMENTS. b buffers stay fp32.
template <int F, int THREADS, bool FINAL, bool GH, bool SH>
__global__ void prop2_kernel(const void* __restrict__ g, int ldG,
                             const __half* __restrict__ addY, int ldA,
                             const void* __restrict__ sub, int ldS,
                             float alpha,
                             float* __restrict__ outF, int ldO4,
                             const float* __restrict__ bias,
                             __half* __restrict__ af, int ldCat) {
    constexpr int F4 = F / 4;
    constexpr int NF = F4 / THREADS;
    static_assert(NF * THREADS == F4, "exact fit required");
    constexpr int ECHUNK = 128;
    __shared__ int   s_col[ECHUNK];
    __shared__ float s_w[ECHUNK];

    int i = blockIdx.x;
    int tid = threadIdx.x;
    bool real = (i < N_NODES);
    int s0 = real ? g_rowptr[i] : 0;
    int s1 = real ? g_rowptr[i + 1] : 0;

    // prefetch addY / sub rows (streamed; overlaps the gather loop)
    float4 addv[NF], subv[NF];
    {
        const __half* arow = addY + (size_t)i * ldA;
#pragma unroll
        for (int j = 0; j < NF; j++) {
            int f4 = (tid + j * THREADS) * 4;
            addv[j] = ldcs4h(arow + f4);
            if (sub) {
                if (SH) subv[j] = ldcs4h((const __half*)sub + (size_t)i * ldS + f4);
                else    subv[j] = ldcs4(reinterpret_cast<const float4*>(
                                        (const float*)sub + (size_t)i * ldS) + (tid + j * THREADS));
            } else subv[j] = make_float4(0.f, 0.f, 0.f, 0.f);
        }
    }

    float ax[NF], ay[NF], az[NF], aw[NF];
#pragma unroll
    for (int j = 0; j < NF; j++) { ax[j] = 0.f; ay[j] = 0.f; az[j] = 0.f; aw[j] = 0.f; }

    int e = s0;
    while (e < s1) {
        int cnt = s1 - e; if (cnt > ECHUNK) cnt = ECHUNK;
        __syncthreads();
        for (int q = tid; q < cnt; q += THREADS) {
            int c = g_colS[e + q];
            s_col[q] = c;
            s_w[q] = g_dis[c];
        }
        __syncthreads();

        int q = 0;
        for (; q + 4 <= cnt; q += 4) {
            int c0 = s_col[q],     c1 = s_col[q + 1];
            int c2 = s_col[q + 2], c3 = s_col[q + 3];
            float w0 = s_w[q],     w1 = s_w[q + 1];
            float w2 = s_w[q + 2], w3 = s_w[q + 3];
#pragma unroll
            for (int j = 0; j < NF; j++) {
                int f = tid + j * THREADS;
                float4 v0, v1, v2, v3;
                if (GH) {
                    const __half* gb = (const __half*)g;
                    v0 = ld4h(gb + (size_t)c0 * ldG + f * 4);
                    v1 = ld4h(gb + (size_t)c1 * ldG + f * 4);
                    v2 = ld4h(gb + (size_t)c2 * ldG + f * 4);
                    v3 = ld4h(gb + (size_t)c3 * ldG + f * 4);
                } else {
                    const float* gb = (const float*)g;
                    v0 = reinterpret_cast<const float4*>(gb + (size_t)c0 * ldG)[f];
                    v1 = reinterpret_cast<const float4*>(gb + (size_t)c1 * ldG)[f];
                    v2 = reinterpret_cast<const float4*>(gb + (size_t)c2 * ldG)[f];
                    v3 = reinterpret_cast<const float4*>(gb + (size_t)c3 * ldG)[f];
                }
                ax[j] += w0 * v0.x + w1 * v1.x + w2 * v2.x + w3 * v3.x;
                ay[j] += w0 * v0.y + w1 * v1.y + w2 * v2.y + w3 * v3.y;
                az[j] += w0 * v0.z + w1 * v1.z + w2 * v2.z + w3 * v3.z;
                aw[j] += w0 * v0.w + w1 * v1.w + w2 * v2.w + w3 * v3.w;
            }
        }
        for (; q < cnt; q++) {
            int c = s_col[q];
            float s = s_w[q];
#pragma unroll
            for (int j = 0; j < NF; j++) {
                int f = tid + j * THREADS;
                float4 v;
                if (GH) v = ld4h((const __half*)g + (size_t)c * ldG + f * 4);
                else    v = reinterpret_cast<const float4*>((const float*)g + (size_t)c * ldG)[f];
                ax[j] += s * v.x; ay[j] += s * v.y;
                az[j] += s * v.z; aw[j] += s * v.w;
            }
        }
        e += cnt;
    }

    float sc = real ? (-alpha * g_dis[i]) : 0.0f;

#pragma unroll
    for (int j = 0; j < NF; j++) {
        int f = tid + j * THREADS;
        float4 r;
        r.x = sc * ax[j] + addv[j].x - subv[j].x;
        r.y = sc * ay[j] + addv[j].y - subv[j].y;
        r.z = sc * az[j] + addv[j].z - subv[j].z;
        r.w = sc * aw[j] + addv[j].w - subv[j].w;
        if (FINAL) {
            if (real) {
                const float4 bv = reinterpret_cast<const float4*>(bias)[f];
                r.x = fmaxf(r.x + bv.x, 0.f); r.y = fmaxf(r.y + bv.y, 0.f);
                r.z = fmaxf(r.z + bv.z, 0.f); r.w = fmaxf(r.w + bv.w, 0.f);
            } else {
                r.x = r.y = r.z = r.w = 0.f;
            }
            if (af) {
                size_t o = (size_t)i * ldCat + (size_t)f * 4;
                __half2* fp = reinterpret_cast<__half2*>(af + o);
                fp[0] = __halves2half2(__float2half_rn(r.x), __float2half_rn(r.y));
                fp[1] = __halves2half2(__float2half_rn(r.z), __float2half_rn(r.w));
            }
            if (outF && real)
                stcs4(reinterpret_cast<float4*>(outF) + (size_t)i * ldO4 + f, r);
        } else {
            // next prop gathers this buffer: default policy (keep in L2)
            reinterpret_cast<float4*>(outF)[(size_t)i * ldO4 + f] = r;
        }
    }
}

// ---------------- single-product fp16 mma.sync GEMM ----------------
// Y[M x N] (fp16 out, ld=ldC halves) = Af16 x Bh16^T, fp32 accumulate.
// 128x128 CTA, 4 warps of 64x64, 3 stages XOR-swizzled, 1 sync/k-tile, 2 CTA/SM
// (occupancy 2: keeps regs uncapped at 256/thread -> no spills).
#define GBK     32
#define TILE_B  (128 * 64)
#define STG_B   (2 * TILE_B)              // A, B tiles only
#define SMEM_TOTAL_GEMM (3 * STG_B)       // 49152

__device__ __forceinline__ uint32_t sw_off(int r, int c16) {
    return (uint32_t)(r * 64 + ((c16 ^ ((r >> 1) & 3)) * 16));
}

__global__ void __launch_bounds__(128, 2)
gemm_fused_kernel(const __half* __restrict__ Af, const __half* __restrict__ Bh,
                  __half* __restrict__ C, int N, int ldC, int K) {
    extern __shared__ char smem[];
    uint32_t sb = smem_u32(smem);
    int tid = threadIdx.x;
    int lane = tid & 31;
    int wid = tid >> 5;
    int bm = blockIdx.y * 128;
    int bn = blockIdx.x * 128;

    const int kt = K / GBK;

    int wm = (wid & 1) * 64;
    int wn = (wid >> 1) * 64;

    float d[4][8][4];
#pragma unroll
    for (int i = 0; i < 4; i++)
#pragma unroll
        for (int j = 0; j < 8; j++)
#pragma unroll
            for (int q = 0; q < 4; q++) d[i][j][q] = 0.f;

    size_t ld = (size_t)K * 2;   // bytes per row
    auto issue = [&](int it) {
        int kk = it * GBK;
        int s = it % 3;
        uint32_t base = sb + s * STG_B;
        const char* srcA = (const char*)(Af + (size_t)bm * K + kk);
        const char* srcB = (const char*)(Bh + (size_t)bn * K + kk);
#pragma unroll
        for (int i = 0; i < 4; i++) {
            int v = tid + i * 128;
            int r = v >> 2, p = v & 3;
            CP_ASYNC16(base + sw_off(r, p), srcA + (size_t)r * ld + p * 16);
        }
#pragma unroll
        for (int i = 0; i < 4; i++) {
            int v = tid + i * 128;
            int r = v >> 2, p = v & 3;
            CP_ASYNC16(base + TILE_B + sw_off(r, p), srcB + (size_t)r * ld + p * 16);
        }
    };

    issue(0); CP_COMMIT();
    if (kt > 1) issue(1);
    CP_COMMIT();

    int lrow = lane & 15;
    int lcol = (lane >> 4) * 8;

    uint32_t arow[4], brow[4];
#pragma unroll
    for (int i = 0; i < 4; i++) {
        int rr = wm + i * 16 + lrow;
        arow[i] = (uint32_t)(rr * 64) | ((uint32_t)((rr >> 1) & 3) << 28);
    }
#pragma unroll
    for (int jp = 0; jp < 4; jp++) {
        int rr = wn + jp * 16 + lrow;
        brow[jp] = (uint32_t)(rr * 64) | ((uint32_t)((rr >> 1) & 3) << 28);
    }

    for (int it = 0; it < kt; ++it) {
        CP_WAIT1();
        __syncthreads();

        if (it + 2 < kt) issue(it + 2);
        CP_COMMIT();

        int s = it % 3;
        uint32_t sA = sb + s * STG_B;
        uint32_t sB = sA + TILE_B;

#pragma unroll
        for (int ks = 0; ks < GBK; ks += 16) {
            uint32_t cch = (uint32_t)((ks + lcol) >> 3);

            uint32_t a[4][4], b[8][2];
#pragma unroll
            for (int i = 0; i < 4; i++) {
                uint32_t off = (arow[i] & 0x0fffffffu) + ((cch ^ (arow[i] >> 28)) << 4);
                LDMATRIX_X4(a[i][0], a[i][1], a[i][2], a[i][3], sA + off);
            }
#pragma unroll
            for (int jp = 0; jp < 4; jp++) {
                uint32_t off = (brow[jp] & 0x0fffffffu) + ((cch ^ (brow[jp] >> 28)) << 4);
                uint32_t q0, q1, q2, q3;
                LDMATRIX_X4(q0, q1, q2, q3, sB + off);
                b[2 * jp][0] = q0; b[2 * jp][1] = q2;
                b[2 * jp + 1][0] = q1; b[2 * jp + 1][1] = q3;
            }
#pragma unroll
            for (int i = 0; i < 4; i++)
#pragma unroll
                for (int j = 0; j < 8; j++)
                    MMA_F16(d[i][j], a[i], b[j]);
        }
    }

    // epilogue: streamed fp16 Y writes (pad rows of A are zero -> Y pad rows zero)
    int gr = lane >> 2;
    int gc = (lane & 3) * 2;
#pragma unroll
    for (int i = 0; i < 4; i++) {
#pragma unroll
        for (int j = 0; j < 8; j++) {
            int colb = bn + wn + j * 8 + gc;
            if (colb >= N) continue;
            int row0 = bm + wm + i * 16 + gr;
            int row1 = row0 + 8;
            stcs_h2(&C[(size_t)row0 * ldC + colb], d[i][j][0], d[i][j][1]);
            stcs_h2(&C[(size_t)row1 * ldC + colb], d[i][j][2], d[i][j][3]);
        }
    }
}

// ---------------- host orchestration ----------------
extern "C" void kernel_launch(void* const* d_in, const int* in_sizes, int n_in,
                              void* d_out, int out_size) {
    const float* x   = (const float*)d_in[0];
    const int*   row = (const int*)d_in[1];
    const int*   col = (const int*)d_in[2];
    const float* W1  = (const float*)d_in[3];
    const float* b1  = (const float*)d_in[4];
    const float* W2  = (const float*)d_in[5];
    const float* b2  = (const float*)d_in[6];
    const float* W3  = (const float*)d_in[7];
    const float* b3  = (const float*)d_in[8];
    float* out = (float*)d_out;

    float *bufA, *bufB, *bufC;
    __half *Y, *A1f, *A2f, *W1h, *W2h, *W3h;
    cudaGetSymbolAddress((void**)&Y, g_Y);
    cudaGetSymbolAddress((void**)&bufA, g_bufA);
    cudaGetSymbolAddress((void**)&bufB, g_bufB);
    cudaGetSymbolAddress((void**)&bufC, g_bufC);
    cudaGetSymbolAddress((void**)&A1f, g_A1f);
    cudaGetSymbolAddress((void**)&A2f, g_A2f);
    cudaGetSymbolAddress((void**)&W1h, g_W1h);
    cudaGetSymbolAddress((void**)&W2h, g_W2h);
    cudaGetSymbolAddress((void**)&W3h, g_W3h);

    cudaFuncSetAttribute(gemm_fused_kernel,
                         cudaFuncAttributeMaxDynamicSharedMemorySize, SMEM_TOTAL_GEMM);

    // ---- graph setup ----
    zero_counts_kernel<<<(N_NODES + 255) / 256, 256>>>();
    hist_kernel<<<(N_EDGES + 255) / 256, 256>>>(row, col);
    scan_kernel<<<1, 1024>>>();
    scatter_kernel<<<(N_EDGES + 255) / 256, 256>>>(row, col);

    // ---- conversions ----
    convert_split_kernel<<<4096, 256>>>(x, F1, A1f);
    wsplit2_kernel<<<dim3(F1 / 32, F1 / 32, 6), dim3(32, 8)>>>(W1, F1, F1, W1h);
    wsplit2_kernel<<<dim3(F1 / 32, F2 / 32, 5), dim3(32, 8)>>>(W2, F1, F2, W2h);
    wsplit2_kernel<<<dim3(F2 / 32, F3 / 32, 5), dim3(32, 8)>>>(W3, F2, F3, W3h);

    // ================= Layer 1: K=6, Fout=1152 =================
    gemm_fused_kernel<<<dim3(NY1 / 128, M_PAD / 128), 128, SMEM_TOTAL_GEMM>>>(
        A1f, W1h, Y, NY1, NY1, F1);
    {
        const int ldY = NY1;            // element stride (halves)
        const int ldF = F1;             // element stride (floats)
        const int ldF4 = F1 / 4;
        // Clenshaw: b5 = Y5; b4..b1; S = Y0 + L~b1 - b2
        prop2_kernel<F1, 96, false, true,  false><<<M_PAD, 96>>>(
            Y + 5 * F1, ldY, Y + 4 * F1, ldY, nullptr, 0, 2.0f, bufA, ldF4, nullptr, nullptr, 0);
        prop2_kernel<F1, 96, false, false, true ><<<M_PAD, 96>>>(
            bufA, ldF, Y + 3 * F1, ldY, Y + 5 * F1, ldY, 2.0f, bufB, ldF4, nullptr, nullptr, 0);
        prop2_kernel<F1, 96, false, false, false><<<M_PAD, 96>>>(
            bufB, ldF, Y + 2 * F1, ldY, bufA, ldF, 2.0f, bufC, ldF4, nullptr, nullptr, 0);
        prop2_kernel<F1, 96, false, false, false><<<M_PAD, 96>>>(
            bufC, ldF, Y + 1 * F1, ldY, bufB, ldF, 2.0f, bufA, ldF4, nullptr, nullptr, 0);
        prop2_kernel<F1, 96, true,  false, false><<<M_PAD, 96>>>(
            bufA, ldF, Y + 0, ldY, bufC, ldF, 1.0f, nullptr, 0, b1, A2f, F1);
    }

    // ================= Layer 2: K=5, Fout=576 =================
    gemm_fused_kernel<<<dim3(NY2P / 128, M_PAD / 128), 128, SMEM_TOTAL_GEMM>>>(
        A2f, W2h, Y, NY2, NY2P, F1);
    {
        const int ldY = NY2P;
        const int ldF = F2;
        const int ldF4 = F2 / 4;
        prop2_kernel<F2, 144, false, true,  false><<<M_PAD, 144>>>(
            Y + 4 * F2, ldY, Y + 3 * F2, ldY, nullptr, 0, 2.0f, bufA, ldF4, nullptr, nullptr, 0);
        prop2_kernel<F2, 144, false, false, true ><<<M_PAD, 144>>>(
            bufA, ldF, Y + 2 * F2, ldY, Y + 4 * F2, ldY, 2.0f, bufB, ldF4, nullptr, nullptr, 0);
        prop2_kernel<F2, 144, false, false, false><<<M_PAD, 144>>>(
            bufB, ldF, Y + 1 * F2, ldY, bufA, ldF, 2.0f, bufC, ldF4, nullptr, nullptr, 0);
        prop2_kernel<F2, 144, true,  false, false><<<M_PAD, 144>>>(
            bufC, ldF, Y + 0, ldY, bufB, ldF, 1.0f, nullptr, 0, b2, A1f, F2);
    }

    // ================= Layer 3: K=5, Fout=288 =================
    gemm_fused_kernel<<<dim3(NY3P / 128, M_PAD / 128), 128, SMEM_TOTAL_GEMM>>>(
        A1f, W3h, Y, NY3, NY3P, F2);
    {
        const int ldY = NY3P;
        const int ldF = F3;
        const int ldF4 = F3 / 4;
        prop2_kernel<F3, 72, false, true,  false><<<M_PAD, 72>>>(
            Y + 4 * F3, ldY, Y + 3 * F3, ldY, nullptr, 0, 2.0f, bufA, ldF4, nullptr, nullptr, 0);
        prop2_kernel<F3, 72, false, false, true ><<<M_PAD, 72>>>(
            bufA, ldF, Y + 2 * F3, ldY, Y + 4 * F3, ldY, 2.0f, bufB, ldF4, nullptr, nullptr, 0);
        prop2_kernel<F3, 72, false, false, false><<<M_PAD, 72>>>(
            bufB, ldF, Y + 1 * F3, ldY, bufA, ldF, 2.0f, bufC, ldF4, nullptr, nullptr, 0);
        prop2_kernel<F3, 72, true,  false, false><<<M_PAD, 72>>>(
            bufC, ldF, Y + 0, ldY, bufB, ldF, 1.0f, out, ldF4, b3, nullptr, 0);
    }
}

// round 17
// speedup vs baseline: 1.1031x; 1.0957x over previous
#include <cuda_runtime.h>
#include <cuda_bf16.h>
#include <cuda_fp16.h>
#include <cstdint>
#include <cstddef>

#define N_NODES 20000
#define N_EDGES 320000
#define M_PAD   20224          // 158 * 128
#define F1 1152
#define F2 576
#define F3 288

// GEMM output (Y-cat) dims: N = K*Fout, padded to /128
#define NY1 6912               // 6*1152, 54*128 exact
#define NY2 2880               // 5*576
#define NY2P 2944              // 23*128
#define NY3 1440               // 5*288
#define NY3P 1536              // 12*128

// ---------------- scratch (device globals; allocation-free) ----------------
__device__ float g_Y[(size_t)M_PAD * NY1];          // Y-cat fp32 (proven faster than fp16)
__device__ float g_bufA[(size_t)M_PAD * F1];        // Clenshaw b buffers (fp32)
__device__ float g_bufB[(size_t)M_PAD * F1];
__device__ float g_bufC[(size_t)M_PAD * F1];

// A ping-pong: fp16 (single-product GEMM)
__device__ __half g_A1f[(size_t)M_PAD * F1];
__device__ __half g_A2f[(size_t)M_PAD * F1];

// B = Wcat^T in fp16
__device__ __half g_W1h[(size_t)NY1 * F1];
__device__ __half g_W2h[(size_t)NY2P * F1];
__device__ __half g_W3h[(size_t)NY3P * F2];

__device__ int   g_deg[N_NODES];
__device__ int   g_fill[N_NODES];
__device__ int   g_rowptr[N_NODES + 1];
__device__ int   g_colS[N_EDGES];
__device__ float g_dis[N_NODES];

// ---------------- PTX helpers (base sm_103 target only) ----------------
__device__ __forceinline__ uint32_t smem_u32(const void* p) {
    uint32_t a;
    asm("{ .reg .u64 t; cvta.to.shared.u64 t, %1; cvt.u32.u64 %0, t; }" : "=r"(a) : "l"(p));
    return a;
}

#define CP_ASYNC16(dst, src) \
    asm volatile("cp.async.cg.shared.global [%0], [%1], 16;" :: "r"(dst), "l"(src) : "memory")
#define CP_COMMIT() asm volatile("cp.async.commit_group;" ::: "memory")
#define CP_WAIT1()  asm volatile("cp.async.wait_group 1;" ::: "memory")

#define LDMATRIX_X4(r0, r1, r2, r3, addr) \
    asm volatile("ldmatrix.sync.aligned.m8n8.x4.shared.b16 {%0,%1,%2,%3}, [%4];" \
                 : "=r"(r0), "=r"(r1), "=r"(r2), "=r"(r3) : "r"(addr))

#define MMA_F16(d, a, b) \
    asm volatile("mma.sync.aligned.m16n8k16.row.col.f32.f16.f16.f32 " \
                 "{%0,%1,%2,%3}, {%4,%5,%6,%7}, {%8,%9}, {%0,%1,%2,%3};" \
                 : "+f"((d)[0]), "+f"((d)[1]), "+f"((d)[2]), "+f"((d)[3]) \
                 : "r"((a)[0]), "r"((a)[1]), "r"((a)[2]), "r"((a)[3]), \
                   "r"((b)[0]), "r"((b)[1]))

// streaming (evict-first) vector load/store
__device__ __forceinline__ float4 ldcs4(const float4* p) {
    float4 v;
    asm volatile("ld.global.cs.v4.f32 {%0,%1,%2,%3}, [%4];"
                 : "=f"(v.x), "=f"(v.y), "=f"(v.z), "=f"(v.w) : "l"(p));
    return v;
}
__device__ __forceinline__ void stcs4(float4* p, float4 v) {
    asm volatile("st.global.cs.v4.f32 [%0], {%1,%2,%3,%4};"
                 :: "l"(p), "f"(v.x), "f"(v.y), "f"(v.z), "f"(v.w) : "memory");
}
__device__ __forceinline__ void stcs2(float2* p, float2 v) {
    asm volatile("st.global.cs.v2.f32 [%0], {%1,%2};"
                 :: "l"(p), "f"(v.x), "f"(v.y) : "memory");
}

// ---------------- graph setup ----------------
__global__ void zero_counts_kernel() {
    int i = blockIdx.x * blockDim.x + threadIdx.x;
    if (i < N_NODES) { g_deg[i] = 0; g_fill[i] = 0; }
}
__global__ void hist_kernel(const int* __restrict__ row, const int* __restrict__ col) {
    int e = blockIdx.x * blockDim.x + threadIdx.x;
    if (e < N_EDGES) {
        int r = row[e];
        if (r != col[e]) atomicAdd(&g_deg[r], 1);
    }
}
// scan + dis fused
__global__ void scan_kernel() {
    __shared__ int sums[1024];
    int t = threadIdx.x;
    const int CHUNK = (N_NODES + 1023) / 1024;
    int lo = t * CHUNK, hi = lo + CHUNK;
    if (hi > N_NODES) hi = N_NODES;
    int s = 0;
    for (int i = lo; i < hi; i++) s += g_deg[i];
    sums[t] = s;
    __syncthreads();
    for (int off = 1; off < 1024; off <<= 1) {
        int v = (t >= off) ? sums[t - off] : 0;
        __syncthreads();
        sums[t] += v;
        __syncthreads();
    }
    int run = (t == 0) ? 0 : sums[t - 1];
    for (int i = lo; i < hi; i++) {
        g_rowptr[i] = run;
        int d = g_deg[i];
        run += d;
        g_dis[i] = (d > 0) ? rsqrtf((float)d) : 0.0f;
    }
    if (t == 1023) g_rowptr[N_NODES] = sums[1023];
}
__global__ void scatter_kernel(const int* __restrict__ row, const int* __restrict__ col) {
    int e = blockIdx.x * blockDim.x + threadIdx.x;
    if (e < N_EDGES) {
        int r = row[e], c = col[e];
        if (r != c) {
            int pos = g_rowptr[r] + atomicAdd(&g_fill[r], 1);
            g_colS[pos] = c;
        }
    }
}

// ---------------- conversion helpers ----------------
__global__ void convert_split_kernel(const float* __restrict__ src, int F,
                                     __half* __restrict__ af) {
    int total = M_PAD * F;
    for (int idx = blockIdx.x * blockDim.x + threadIdx.x; idx < total;
         idx += gridDim.x * blockDim.x) {
        int r = idx / F, c = idx - r * F;
        float v = (r < N_NODES) ? src[(size_t)r * F + c] : 0.0f;
        af[(size_t)r * F + c] = __float2half_rn(v);
    }
}

__global__ void wsplit2_kernel(const float* __restrict__ W, int Fin, int Fout,
                               __half* __restrict__ hi) {
    __shared__ float tile[32][33];
    int kk0 = blockIdx.x * 32, n0 = blockIdx.y * 32, k = blockIdx.z;
    int tx = threadIdx.x, ty = threadIdx.y;
    const float* Wk = W + (size_t)k * Fin * Fout;
#pragma unroll
    for (int r = 0; r < 32; r += 8)
        tile[ty + r][tx] = Wk[(size_t)(kk0 + ty + r) * Fout + n0 + tx];
    __syncthreads();
#pragma unroll
    for (int r = 0; r < 32; r += 8) {
        float v = tile[tx][ty + r];
        size_t o = (size_t)(k * Fout + n0 + ty + r) * Fin + kk0 + tx;
        hi[o] = __float2half_rn(v);
    }
}

// ---------------- Clenshaw propagation (fp32 everywhere) ----------------
// out = alpha*(L~ g) + addY - sub   (sub nullable)
// addY/sub streamed (evict-first); gather source stays L2-resident.
// MID:   write fp32 out default policy (next prop gathers it -> keep in L2)
// FINAL: r = real ? relu(r + bias) : 0; write fp16 A copy (if af != null)
//        and fp32 outF (streamed) guarded to i < N_NODES (if outF != null)
template <int F, int THREADS, bool FINAL>
__global__ void prop2_kernel(const float* __restrict__ g, int ldG4,
                             const float* __restrict__ addY, int ldA4,
                             const float* __restrict__ sub, int ldS4,
                             float alpha,
                             float* __restrict__ outF, int ldO4,
                             const float* __restrict__ bias,
                             __half* __restrict__ af, int ldCat) {
    constexpr int F4 = F / 4;
    constexpr int NF = F4 / THREADS;
    static_assert(NF * THREADS == F4, "exact fit required");
    constexpr int ECHUNK = 128;
    __shared__ int   s_col[ECHUNK];
    __shared__ float s_w[ECHUNK];

    int i = blockIdx.x;
    int tid = threadIdx.x;
    bool real = (i < N_NODES);
    int s0 = real ? g_rowptr[i] : 0;
    int s1 = real ? g_rowptr[i + 1] : 0;

    // prefetch addY / sub rows with streaming hint (read-once data)
    float4 addv[NF], subv[NF];
    {
        const float4* arow = reinterpret_cast<const float4*>(addY) + (size_t)i * ldA4;
        const float4* srow = sub ? (reinterpret_cast<const float4*>(sub) + (size_t)i * ldS4)
                                 : nullptr;
#pragma unroll
        for (int j = 0; j < NF; j++) {
            int f = tid + j * THREADS;
            addv[j] = ldcs4(arow + f);
            subv[j] = srow ? ldcs4(srow + f) : make_float4(0.f, 0.f, 0.f, 0.f);
        }
    }

    float ax[NF], ay[NF], az[NF], aw[NF];
#pragma unroll
    for (int j = 0; j < NF; j++) { ax[j] = 0.f; ay[j] = 0.f; az[j] = 0.f; aw[j] = 0.f; }

    int e = s0;
    while (e < s1) {
        int cnt = s1 - e; if (cnt > ECHUNK) cnt = ECHUNK;
        __syncthreads();
        for (int q = tid; q < cnt; q += THREADS) {
            int c = g_colS[e + q];
            s_col[q] = c;
            s_w[q] = g_dis[c];
        }
        __syncthreads();

        int q = 0;
        for (; q + 4 <= cnt; q += 4) {
            int c0 = s_col[q],     c1 = s_col[q + 1];
            int c2 = s_col[q + 2], c3 = s_col[q + 3];
            float w0 = s_w[q],     w1 = s_w[q + 1];
            float w2 = s_w[q + 2], w3 = s_w[q + 3];
            const float4* t0 = reinterpret_cast<const float4*>(g) + (size_t)c0 * ldG4;
            const float4* t1 = reinterpret_cast<const float4*>(g) + (size_t)c1 * ldG4;
            const float4* t2 = reinterpret_cast<const float4*>(g) + (size_t)c2 * ldG4;
            const float4* t3 = reinterpret_cast<const float4*>(g) + (size_t)c3 * ldG4;
#pragma unroll
            for (int j = 0; j < NF; j++) {
                int f = tid + j * THREADS;
                float4 v0 = t0[f];
                float4 v1 = t1[f];
                float4 v2 = t2[f];
                float4 v3 = t3[f];
                ax[j] += w0 * v0.x + w1 * v1.x + w2 * v2.x + w3 * v3.x;
                ay[j] += w0 * v0.y + w1 * v1.y + w2 * v2.y + w3 * v3.y;
                az[j] += w0 * v0.z + w1 * v1.z + w2 * v2.z + w3 * v3.z;
                aw[j] += w0 * v0.w + w1 * v1.w + w2 * v2.w + w3 * v3.w;
            }
        }
        for (; q < cnt; q++) {
            int c = s_col[q];
            float s = s_w[q];
            const float4* tr = reinterpret_cast<const float4*>(g) + (size_t)c * ldG4;
#pragma unroll
            for (int j = 0; j < NF; j++) {
                int f = tid + j * THREADS;
                float4 v = tr[f];
                ax[j] += s * v.x; ay[j] += s * v.y;
                az[j] += s * v.z; aw[j] += s * v.w;
            }
        }
        e += cnt;
    }

    float sc = real ? (-alpha * g_dis[i]) : 0.0f;

#pragma unroll
    for (int j = 0; j < NF; j++) {
        int f = tid + j * THREADS;
        float4 r;
        r.x = sc * ax[j] + addv[j].x - subv[j].x;
        r.y = sc * ay[j] + addv[j].y - subv[j].y;
        r.z = sc * az[j] + addv[j].z - subv[j].z;
        r.w = sc * aw[j] + addv[j].w - subv[j].w;
        if (FINAL) {
            if (real) {
                const float4 bv = reinterpret_cast<const float4*>(bias)[f];
                r.x = fmaxf(r.x + bv.x, 0.f); r.y = fmaxf(r.y + bv.y, 0.f);
                r.z = fmaxf(r.z + bv.z, 0.f); r.w = fmaxf(r.w + bv.w, 0.f);
            } else {
                r.x = r.y = r.z = r.w = 0.f;
            }
            if (af) {
                size_t o = (size_t)i * ldCat + (size_t)f * 4;
                __half2* fp = reinterpret_cast<__half2*>(af + o);
                fp[0] = __halves2half2(__float2half_rn(r.x), __float2half_rn(r.y));
                fp[1] = __halves2half2(__float2half_rn(r.z), __float2half_rn(r.w));
            }
            if (outF && real)
                stcs4(reinterpret_cast<float4*>(outF) + (size_t)i * ldO4 + f, r);
        } else {
            // next prop gathers this buffer: default policy (keep in L2)
            reinterpret_cast<float4*>(outF)[(size_t)i * ldO4 + f] = r;
        }
    }
}

// ---------------- single-product fp16 mma.sync GEMM (BK=64) ----------------
// Y[M x N] (fp32, ld=ldC) = Af16 x Bh16^T, fp32 accumulate.
// 128x128 CTA, 4 warps of 64x64, 3 stages, 128B-row XOR swizzle,
// 1 sync per 64-wide k-tile (half the barriers of BK=32), 2 CTA/SM.
#define GBK     64
#define TILE_B  (128 * 128)               // 16384: 128 rows x 128 bytes
#define STG_B   (2 * TILE_B)              // 32768: A, B tiles
#define SMEM_TOTAL_GEMM (3 * STG_B)       // 98304; x2 CTAs = 192KB <= 227KB

// 128B-row swizzle: chunk c16 in 0..7, XOR with (r & 7); conflict-free for
// ldmatrix (8 consecutive rows per phase -> 8 distinct chunk columns).
__device__ __forceinline__ uint32_t sw_off(int r, int c16) {
    return (uint32_t)(r * 128 + ((c16 ^ (r & 7)) * 16));
}

__global__ void __launch_bounds__(128, 2)
gemm_fused_kernel(const __half* __restrict__ Af, const __half* __restrict__ Bh,
                  float* __restrict__ C, int N, int ldC, int K) {
    extern __shared__ char smem[];
    uint32_t sb = smem_u32(smem);
    int tid = threadIdx.x;
    int lane = tid & 31;
    int wid = tid >> 5;
    int bm = blockIdx.y * 128;
    int bn = blockIdx.x * 128;

    const int kt = K / GBK;

    int wm = (wid & 1) * 64;
    int wn = (wid >> 1) * 64;

    float d[4][8][4];
#pragma unroll
    for (int i = 0; i < 4; i++)
#pragma unroll
        for (int j = 0; j < 8; j++)
#pragma unroll
            for (int q = 0; q < 4; q++) d[i][j][q] = 0.f;

    size_t ld = (size_t)K * 2;   // bytes per row
    auto issue = [&](int it) {
        int kk = it * GBK;
        int s = it % 3;
        uint32_t base = sb + s * STG_B;
        const char* srcA = (const char*)(Af + (size_t)bm * K + kk);
        const char* srcB = (const char*)(Bh + (size_t)bn * K + kk);
        // 128 rows x 8 chunks of 16B = 1024 chunks per tile; 8 per thread
#pragma unroll
        for (int i = 0; i < 8; i++) {
            int v = tid + i * 128;
            int r = v >> 3, p = v & 7;
            CP_ASYNC16(base + sw_off(r, p), srcA + (size_t)r * ld + p * 16);
        }
#pragma unroll
        for (int i = 0; i < 8; i++) {
            int v = tid + i * 128;
            int r = v >> 3, p = v & 7;
            CP_ASYNC16(base + TILE_B + sw_off(r, p), srcB + (size_t)r * ld + p * 16);
        }
    };

    issue(0); CP_COMMIT();
    if (kt > 1) issue(1);
    CP_COMMIT();

    int lrow = lane & 15;
    int lcol = (lane >> 4) * 8;

    // row-base | xor-key (r & 7) in high nibble
    uint32_t arow[4], brow[4];
#pragma unroll
    for (int i = 0; i < 4; i++) {
        int rr = wm + i * 16 + lrow;
        arow[i] = (uint32_t)(rr * 128) | ((uint32_t)(rr & 7) << 28);
    }
#pragma unroll
    for (int jp = 0; jp < 4; jp++) {
        int rr = wn + jp * 16 + lrow;
        brow[jp] = (uint32_t)(rr * 128) | ((uint32_t)(rr & 7) << 28);
    }

    for (int it = 0; it < kt; ++it) {
        CP_WAIT1();
        __syncthreads();

        if (it + 2 < kt) issue(it + 2);
        CP_COMMIT();

        int s = it % 3;
        uint32_t sA = sb + s * STG_B;
        uint32_t sB = sA + TILE_B;

#pragma unroll
        for (int ks = 0; ks < GBK; ks += 16) {
            uint32_t cch = (uint32_t)((ks + lcol) >> 3);   // 16B chunk 0..7

            uint32_t a[4][4], b[8][2];
#pragma unroll
            for (int i = 0; i < 4; i++) {
                uint32_t off = (arow[i] & 0x0fffffffu) + ((cch ^ (arow[i] >> 28)) << 4);
                LDMATRIX_X4(a[i][0], a[i][1], a[i][2], a[i][3], sA + off);
            }
#pragma unroll
            for (int jp = 0; jp < 4; jp++) {
                uint32_t off = (brow[jp] & 0x0fffffffu) + ((cch ^ (brow[jp] >> 28)) << 4);
                uint32_t q0, q1, q2, q3;
                LDMATRIX_X4(q0, q1, q2, q3, sB + off);
                b[2 * jp][0] = q0; b[2 * jp][1] = q2;
                b[2 * jp + 1][0] = q1; b[2 * jp + 1][1] = q3;
            }
#pragma unroll
            for (int i = 0; i < 4; i++)
#pragma unroll
                for (int j = 0; j < 8; j++)
                    MMA_F16(d[i][j], a[i], b[j]);
        }
    }

    // epilogue: streamed fp32 Y writes (pad rows of A are zero -> Y pad rows zero)
    int gr = lane >> 2;
    int gc = (lane & 3) * 2;
#pragma unroll
    for (int i = 0; i < 4; i++) {
#pragma unroll
        for (int j = 0; j < 8; j++) {
            int colb = bn + wn + j * 8 + gc;
            if (colb >= N) continue;
            int row0 = bm + wm + i * 16 + gr;
            int row1 = row0 + 8;
            float2 v0; v0.x = d[i][j][0]; v0.y = d[i][j][1];
            float2 v1; v1.x = d[i][j][2]; v1.y = d[i][j][3];
            stcs2(reinterpret_cast<float2*>(&C[(size_t)row0 * ldC + colb]), v0);
            stcs2(reinterpret_cast<float2*>(&C[(size_t)row1 * ldC + colb]), v1);
        }
    }
}

// ---------------- host orchestration ----------------
extern "C" void kernel_launch(void* const* d_in, const int* in_sizes, int n_in,
                              void* d_out, int out_size) {
    const float* x   = (const float*)d_in[0];
    const int*   row = (const int*)d_in[1];
    const int*   col = (const int*)d_in[2];
    const float* W1  = (const float*)d_in[3];
    const float* b1  = (const float*)d_in[4];
    const float* W2  = (const float*)d_in[5];
    const float* b2  = (const float*)d_in[6];
    const float* W3  = (const float*)d_in[7];
    const float* b3  = (const float*)d_in[8];
    float* out = (float*)d_out;

    float *Y, *bufA, *bufB, *bufC;
    __half *A1f, *A2f, *W1h, *W2h, *W3h;
    cudaGetSymbolAddress((void**)&Y, g_Y);
    cudaGetSymbolAddress((void**)&bufA, g_bufA);
    cudaGetSymbolAddress((void**)&bufB, g_bufB);
    cudaGetSymbolAddress((void**)&bufC, g_bufC);
    cudaGetSymbolAddress((void**)&A1f, g_A1f);
    cudaGetSymbolAddress((void**)&A2f, g_A2f);
    cudaGetSymbolAddress((void**)&W1h, g_W1h);
    cudaGetSymbolAddress((void**)&W2h, g_W2h);
    cudaGetSymbolAddress((void**)&W3h, g_W3h);

    cudaFuncSetAttribute(gemm_fused_kernel,
                         cudaFuncAttributeMaxDynamicSharedMemorySize, SMEM_TOTAL_GEMM);

    // ---- graph setup ----
    zero_counts_kernel<<<(N_NODES + 255) / 256, 256>>>();
    hist_kernel<<<(N_EDGES + 255) / 256, 256>>>(row, col);
    scan_kernel<<<1, 1024>>>();
    scatter_kernel<<<(N_EDGES + 255) / 256, 256>>>(row, col);

    // ---- conversions ----
    convert_split_kernel<<<4096, 256>>>(x, F1, A1f);
    wsplit2_kernel<<<dim3(F1 / 32, F1 / 32, 6), dim3(32, 8)>>>(W1, F1, F1, W1h);
    wsplit2_kernel<<<dim3(F1 / 32, F2 / 32, 5), dim3(32, 8)>>>(W2, F1, F2, W2h);
    wsplit2_kernel<<<dim3(F2 / 32, F3 / 32, 5), dim3(32, 8)>>>(W3, F2, F3, W3h);

    // ================= Layer 1: K=6, Fout=1152 =================
    gemm_fused_kernel<<<dim3(NY1 / 128, M_PAD / 128), 128, SMEM_TOTAL_GEMM>>>(
        A1f, W1h, Y, NY1, NY1, F1);
    {
        const int ldY = NY1 / 4;        // 1728
        const int ldF = F1 / 4;         // 288
        // Clenshaw: b5 = Y5; b4..b1; S = Y0 + L~b1 - b2
        prop2_kernel<F1, 96, false><<<M_PAD, 96>>>(Y + 5 * F1, ldY, Y + 4 * F1, ldY,
                                                   nullptr, 0, 2.0f, bufA, ldF,
                                                   nullptr, nullptr, 0);
        prop2_kernel<F1, 96, false><<<M_PAD, 96>>>(bufA, ldF, Y + 3 * F1, ldY,
                                                   Y + 5 * F1, ldY, 2.0f, bufB, ldF,
                                                   nullptr, nullptr, 0);
        prop2_kernel<F1, 96, false><<<M_PAD, 96>>>(bufB, ldF, Y + 2 * F1, ldY,
                                                   bufA, ldF, 2.0f, bufC, ldF,
                                                   nullptr, nullptr, 0);
        prop2_kernel<F1, 96, false><<<M_PAD, 96>>>(bufC, ldF, Y + 1 * F1, ldY,
                                                   bufB, ldF, 2.0f, bufA, ldF,
                                                   nullptr, nullptr, 0);
        prop2_kernel<F1, 96, true ><<<M_PAD, 96>>>(bufA, ldF, Y + 0, ldY,
                                                   bufC, ldF, 1.0f, nullptr, 0,
                                                   b1, A2f, F1);
    }

    // ================= Layer 2: K=5, Fout=576 =================
    gemm_fused_kernel<<<dim3(NY2P / 128, M_PAD / 128), 128, SMEM_TOTAL_GEMM>>>(
        A2f, W2h, Y, NY2, NY2P, F1);
    {
        const int ldY = NY2P / 4;       // 736
        const int ldF = F2 / 4;         // 144
        prop2_kernel<F2, 144, false><<<M_PAD, 144>>>(Y + 4 * F2, ldY, Y + 3 * F2, ldY,
                                                     nullptr, 0, 2.0f, bufA, ldF,
                                                     nullptr, nullptr, 0);
        prop2_kernel<F2, 144, false><<<M_PAD, 144>>>(bufA, ldF, Y + 2 * F2, ldY,
                                                     Y + 4 * F2, ldY, 2.0f, bufB, ldF,
                                                     nullptr, nullptr, 0);
        prop2_kernel<F2, 144, false><<<M_PAD, 144>>>(bufB, ldF, Y + 1 * F2, ldY,
                                                     bufA, ldF, 2.0f, bufC, ldF,
                                                     nullptr, nullptr, 0);
        prop2_kernel<F2, 144, true ><<<M_PAD, 144>>>(bufC, ldF, Y + 0, ldY,
                                                     bufB, ldF, 1.0f, nullptr, 0,
                                                     b2, A1f, F2);
    }

    // ================= Layer 3: K=5, Fout=288 =================
    gemm_fused_kernel<<<dim3(NY3P / 128, M_PAD / 128), 128, SMEM_TOTAL_GEMM>>>(
        A1f, W3h, Y, NY3, NY3P, F2);
    {
        const int ldY = NY3P / 4;       // 384
        const int ldF = F3 / 4;         // 72
        prop2_kernel<F3, 72, false><<<M_PAD, 72>>>(Y + 4 * F3, ldY, Y + 3 * F3, ldY,
                                                   nullptr, 0, 2.0f, bufA, ldF,
                                                   nullptr, nullptr, 0);
        prop2_kernel<F3, 72, false><<<M_PAD, 72>>>(bufA, ldF, Y + 2 * F3, ldY,
                                                   Y + 4 * F3, ldY, 2.0f, bufB, ldF,
                                                   nullptr, nullptr, 0);
        prop2_kernel<F3, 72, false><<<M_PAD, 72>>>(bufB, ldF, Y + 1 * F3, ldY,
                                                   bufA, ldF, 2.0f, bufC, ldF,
                                                   nullptr, nullptr, 0);
        prop2_kernel<F3, 72, true ><<<M_PAD, 72>>>(bufC, ldF, Y + 0, ldY,
                                                   bufB, ldF, 1.0f, out, ldF,
                                                   b3, nullptr, 0);
    }
}